// round 16
// baseline (speedup 1.0000x reference)
#include <cuda_runtime.h>
#include <math.h>

// Sizes: B=2, Cin=32, G=V=M=4, H=W=28, P=7, MID=48, HEADS=4, POS=16, Cout=64
// q/k/v layout: [(b*4+h)*4+g][yx][48c]
// g_pe: [v*49+kl][32c] (row 0..15, col 16..31)
// g_ge: [(v*4+g)*4+m][16c]
// g_part: [h][b][v*784+yx][64 o]  per-h partial output projection

__device__ float g_q[1204224];
__device__ float g_k[1204224];
__device__ float g_v[1204224];
__device__ float g_pe[6272];
__device__ float g_ge[1024];
__device__ float g_part[1605632];   // 4*2*3136*64

// packed f32x2 helpers (sm_103a FFMA2)
#define PACK2(d, x, y) \
    asm("mov.b64 %0, {%1, %2};" : "=l"(d) \
        : "r"(__float_as_uint(x)), "r"(__float_as_uint(y)))
#define FMA2(d, a, b, c) \
    asm("fma.rn.f32x2 %0, %1, %2, %3;" : "=l"(d) : "l"(a), "l"(b), "l"(c))
#define UNPACK2(x, y, s) do { unsigned int _lo, _hi; \
    asm("mov.b64 {%0, %1}, %2;" : "=r"(_lo), "=r"(_hi) : "l"(s)); \
    (x) = __uint_as_float(_lo); (y) = __uint_as_float(_hi); } while (0)

// ---------------------------------------------------------------------------
// PE MLP
// ---------------------------------------------------------------------------
__device__ __forceinline__ void pe_mlp(float tval,
    const float* __restrict__ w1, const float* __restrict__ b1,
    const float* __restrict__ lng, const float* __restrict__ lnb,
    const float* __restrict__ w2, const float* __restrict__ b2,
    float* outp)
{
    float hv[16];
    float mu = 0.f;
#pragma unroll
    for (int j = 0; j < 16; ++j) { hv[j] = tval * w1[j] + b1[j]; mu += hv[j]; }
    mu *= (1.f / 16.f);
    float var = 0.f;
#pragma unroll
    for (int j = 0; j < 16; ++j) { float d = hv[j] - mu; var += d * d; }
    var *= (1.f / 16.f);
    float rstd = rsqrtf(var + 1e-5f);
#pragma unroll
    for (int j = 0; j < 16; ++j) {
        float t = (hv[j] - mu) * rstd * lng[j] + lnb[j];
        hv[j] = t / (1.f + expf(-t));
    }
#pragma unroll
    for (int j = 0; j < 16; ++j) {
        float e = b2[j];
#pragma unroll
        for (int t = 0; t < 16; ++t) e += hv[t] * w2[j * 16 + t];
        outp[j] = e;
    }
}

__global__ void pe_kernel(
    const float* __restrict__ rw1, const float* __restrict__ rb1,
    const float* __restrict__ rlg, const float* __restrict__ rlb,
    const float* __restrict__ rw2, const float* __restrict__ rb2,
    const float* __restrict__ cw1, const float* __restrict__ cb1,
    const float* __restrict__ clg, const float* __restrict__ clb,
    const float* __restrict__ cw2, const float* __restrict__ cb2,
    const float* __restrict__ ridx, const float* __restrict__ cidx,
    const float* __restrict__ gemb, const int* __restrict__ gidx)
{
    int tid = threadIdx.x;
    if (tid < 196) {
        float er[16], ec[16];
        pe_mlp(ridx[tid], rw1, rb1, rlg, rlb, rw2, rb2, er);
        pe_mlp(cidx[tid], cw1, cb1, clg, clb, cw2, cb2, ec);
#pragma unroll
        for (int j = 0; j < 16; ++j) {
            g_pe[tid * 32 + j]      = er[j];
            g_pe[tid * 32 + 16 + j] = ec[j];
        }
    }
    for (int e = tid; e < 1024; e += blockDim.x) {
        int vgm = e >> 4, c = e & 15;
        g_ge[e] = gemb[gidx[vgm] * 16 + c];
    }
}

// ---------------------------------------------------------------------------
// proj: C[576 x 6272] = [Wq;Wk;Wv][576x32] * X[32x6272] -> g_q/k/v
// ---------------------------------------------------------------------------
__global__ void __launch_bounds__(256) proj_kernel(
    const float* __restrict__ x,
    const float* __restrict__ Wq, const float* __restrict__ bq,
    const float* __restrict__ Wk, const float* __restrict__ bk,
    const float* __restrict__ Wv, const float* __restrict__ bv)
{
    __shared__ float As[32 * 68];
    __shared__ float Bs[32 * 68];
    int tid = threadIdx.x;
    int n0 = blockIdx.x * 64;
    int r0 = blockIdx.y * 64;
    int which = r0 / 192;
    const float* Wm = (which == 0) ? Wq : (which == 1 ? Wk : Wv);
    const float* bias_p = (which == 0) ? bq : (which == 1 ? bk : bv);
    float* dst = (which == 0) ? g_q : (which == 1 ? g_k : g_v);
    int rbase = r0 - which * 192;
    int cbase = rbase >> 2;

#pragma unroll
    for (int k = 0; k < 8; ++k) {
        int i = tid + k * 256;
        int ci = i & 31, row = i >> 5;
        int r = rbase + row;
        int c_l = row >> 2, hh = row & 3;
        int s = (c_l >> 2) * 16 + hh * 4 + (c_l & 3);
        As[ci * 68 + s] = Wm[r * 32 + ci];
    }
#pragma unroll
    for (int k = 0; k < 8; ++k) {
        int i = tid + k * 256;
        int nl = i & 63, ci = i >> 6;
        int n = n0 + nl;
        int bb = n / 3136, rem = n - bb * 3136;
        Bs[ci * 68 + nl] = x[bb * 100352 + ci * 3136 + rem];
    }
    __syncthreads();

    int tx = tid & 15, ty = tid >> 4;
    float acc[4][4] = {};
#pragma unroll
    for (int ci = 0; ci < 32; ++ci) {
        float4 a4 = *(const float4*)&As[ci * 68 + ty * 4];
        float4 b4 = *(const float4*)&Bs[ci * 68 + tx * 4];
        float av[4] = { a4.x, a4.y, a4.z, a4.w };
        float bw[4] = { b4.x, b4.y, b4.z, b4.w };
#pragma unroll
        for (int u = 0; u < 4; ++u)
#pragma unroll
            for (int w = 0; w < 4; ++w) acc[u][w] += av[u] * bw[w];
    }

    int cq = ty >> 2, hh = ty & 3;
    int c0 = cbase + cq * 4;
    float b0 = bias_p[(c0 + 0) * 4 + hh];
    float b1 = bias_p[(c0 + 1) * 4 + hh];
    float b2 = bias_p[(c0 + 2) * 4 + hh];
    float b3 = bias_p[(c0 + 3) * 4 + hh];
#pragma unroll
    for (int w = 0; w < 4; ++w) {
        int n = n0 + tx * 4 + w;
        int bb = n / 3136, rem = n - bb * 3136;
        int gg = rem / 784, yx = rem - gg * 784;
        float4 val = make_float4(acc[0][w] + b0, acc[1][w] + b1,
                                 acc[2][w] + b2, acc[3][w] + b3);
        *(float4*)&dst[(((bb * 4 + hh) * 4 + gg) * 784 + yx) * 48 + c0] = val;
    }
}

// ---------------------------------------------------------------------------
// attn: one block per (b,h, 4x4 pixel tile). 512 threads = 16 warps = 1 site/warp.
// f32x2-packed FMA in content / rc / combine.
// ---------------------------------------------------------------------------
#define SM_PE    0        // [196][36]
#define SM_GE    7056     // [64][16]
#define SM_QS    8080     // [16 sites][196] (reused as ov[c][4v] in combine)
#define SM_SLAB  11216    // [48 c][401]  pos = m*100 + sy*10 + sx
#define SM_RC    30464    // [16 sites][788]; reused as Wout staging after softmax
#define SM_SCR   43072    // per-warp: w 784 | gs 64 = 848
#define SCR_WARP 848
#define ATTN_SMEM_FLOATS (SM_SCR + 16 * SCR_WARP)  // 56640
#define ATTN_SMEM_BYTES  (ATTN_SMEM_FLOATS * 4)    // 226560

// synchronous slab loader (k)
__device__ __forceinline__ void load_slab(float* slab, const float* __restrict__ src,
                                          int bh, int ty0, int tx0, int tid)
{
    if (tid < 480) {
        int c  = tid % 48;
        int sx = tid / 48;                       // 0..9
        int xx = tx0 - 3 + sx;
        bool xok = (unsigned)xx < 28u;
        float* sdst = slab + c * 401 + sx;
        const float* gbase = src + (bh * 4) * 37632 + xx * 48 + c;
#pragma unroll
        for (int m = 0; m < 4; ++m) {
#pragma unroll
            for (int sy = 0; sy < 10; ++sy) {
                int y = ty0 - 3 + sy;
                float val = 0.f;
                if (xok && (unsigned)y < 28u)
                    val = gbase[m * 37632 + y * 1344];
                sdst[m * 100 + sy * 10] = val;
            }
        }
    }
}

// async slab loader (v)
__device__ __forceinline__ void load_slab_async(float* slab, const float* __restrict__ src,
                                                int bh, int ty0, int tx0, int tid)
{
    if (tid < 480) {
        int c  = tid % 48;
        int sx = tid / 48;
        int xx = tx0 - 3 + sx;
        bool xok = (unsigned)xx < 28u;
        int xc = xok ? xx : 0;
        unsigned int sdst = (unsigned int)__cvta_generic_to_shared(slab + c * 401 + sx);
        const float* gbase = src + (bh * 4) * 37632 + xc * 48 + c;
#pragma unroll
        for (int m = 0; m < 4; ++m) {
#pragma unroll
            for (int sy = 0; sy < 10; ++sy) {
                int y = ty0 - 3 + sy;
                bool ok = xok && ((unsigned)y < 28u);
                int yc = ok ? y : 0;
                const float* gp = gbase + m * 37632 + yc * 1344;
                unsigned int sa = sdst + (unsigned int)((m * 100 + sy * 10) * 4);
                int sz = ok ? 4 : 0;
                asm volatile("cp.async.ca.shared.global [%0], [%1], 4, %2;\n"
                             :: "r"(sa), "l"(gp), "r"(sz));
            }
        }
    }
    asm volatile("cp.async.commit_group;\n" ::: "memory");
}

__global__ void __launch_bounds__(512, 1) attn_kernel(const float* __restrict__ Wout)
{
    extern __shared__ float sm[];
    float* pes  = sm + SM_PE;
    float* ges  = sm + SM_GE;
    float* qs   = sm + SM_QS;
    float* slab = sm + SM_SLAB;
    float* rc   = sm + SM_RC;

    const int tid  = threadIdx.x, lane = tid & 31, warp = tid >> 5;
    const int tile = blockIdx.x % 49;
    const int bh   = blockIdx.x / 49;
    const int b    = bh >> 2, h = bh & 3;
    const int ty0  = (tile / 7) * 4, tx0 = (tile % 7) * 4;

    for (int i = tid; i < 6272; i += 512) pes[(i >> 5) * 36 + (i & 31)] = g_pe[i];
    for (int i = tid; i < 1024; i += 512) ges[i] = g_ge[i];
    for (int i = tid; i < 3072; i += 512) {
        int site = i / 192, r = i - site * 192, gg = r / 48, c = r - gg * 48;
        int yx = (ty0 + (site >> 2)) * 28 + tx0 + (site & 3);
        qs[site * 196 + r] = g_q[((bh * 4 + gg) * 784 + yx) * 48 + c];
    }
    load_slab(slab, g_k, bh, ty0, tx0, tid);
    __syncthreads();

    float* scr  = sm + SM_SCR + warp * SCR_WARP;
    float* w_s  = scr;            // 784: [196 p][4 v]
    float* gs_s = scr + 784;      // 64 : [v][g][4 m]

    const int site = warp;
    const int ly = site >> 2, lx = site & 3;
    const float* qsi = qs + site * 196;

    // =============== Phase 1a: group scores gs[v][g][m] (per-warp) =========
#pragma unroll
    for (int u = 0; u < 2; ++u) {
        int e = lane * 2 + u;
        int gg = (e >> 2) & 3;
        float a = 0.f;
#pragma unroll
        for (int c = 0; c < 16; ++c)
            a += qsi[gg * 48 + 32 + c] * ges[e * 16 + c];
        gs_s[e] = a;
    }

    // per-lane entry mapping: p = lane + 32*t over 196 = 4m x 49kl
    int kl_t[7], m_t[7], pos_t[7];
    bool valid[7], act[7];
#pragma unroll
    for (int t = 0; t < 7; ++t) {
        int p = lane + 32 * t;
        act[t] = (p < 196);
        int pc = act[t] ? p : 0;
        int m = pc / 49, kl = pc - m * 49, kk = kl / 7, ll = kl - kk * 7;
        kl_t[t] = kl; m_t[t] = m;
        pos_t[t] = m * 100 + (ly + kk) * 10 + (lx + ll);
        int y = ty0 + ly + kk - 3, xx = tx0 + lx + ll - 3;
        valid[t] = act[t] && ((unsigned)y < 28u) && ((unsigned)xx < 28u);
    }

    // =============== Phase 1b: content via FFMA2 ============================
    float acc[4][7];
    {
        unsigned long long a01[7], a23[7];
#pragma unroll
        for (int t = 0; t < 7; ++t) { a01[t] = 0ull; a23[t] = 0ull; }
        const float4* q4p = (const float4*)qsi;
        for (int c4 = 0; c4 < 12; ++c4) {
            float4 qa = q4p[c4], qb = q4p[12 + c4], qc = q4p[24 + c4], qd = q4p[36 + c4];
            float qr[4][4] = { { qa.x, qa.y, qa.z, qa.w },
                               { qb.x, qb.y, qb.z, qb.w },
                               { qc.x, qc.y, qc.z, qc.w },
                               { qd.x, qd.y, qd.z, qd.w } };
#pragma unroll
            for (int u = 0; u < 4; ++u) {
                unsigned long long qp01, qp23;
                PACK2(qp01, qr[0][u], qr[1][u]);
                PACK2(qp23, qr[2][u], qr[3][u]);
                const float* sr = slab + (c4 * 4 + u) * 401;
#pragma unroll
                for (int t = 0; t < 7; ++t) {
                    float sv = sr[pos_t[t]];
                    unsigned long long svp;
                    PACK2(svp, sv, sv);
                    FMA2(a01[t], qp01, svp, a01[t]);
                    FMA2(a23[t], qp23, svp, a23[t]);
                }
            }
        }
#pragma unroll
        for (int t = 0; t < 7; ++t) {
            UNPACK2(acc[0][t], acc[1][t], a01[t]);
            UNPACK2(acc[2][t], acc[3][t], a23[t]);
        }
    }

    // k-slab reads complete; start async v-slab refill
    __syncthreads();
    load_slab_async(slab, g_v, bh, ty0, tx0, tid);

    // =============== Phase 1c: cooperative rc via FFMA2 =====================
    {
        int colStart = warp * 12 + (warp < 4 ? warp : 4);
        int nCols = (warp < 4) ? 13 : 12;
#pragma unroll 1
        for (int pass = 0; pass < 2; ++pass) {
            int row = pass * 32 + lane;          // (site,g)
            int rsite = row >> 2, rg = row & 3;
            unsigned long long qp[16];
            const float4* q4 = (const float4*)(qs + rsite * 196 + rg * 48);
#pragma unroll
            for (int j = 0; j < 8; ++j) {
                float4 t4 = q4[j];
                PACK2(qp[j * 2],     t4.x, t4.y);
                PACK2(qp[j * 2 + 1], t4.z, t4.w);
            }
            float* rcrow = rc + rsite * 788 + rg * 49;
            for (int cc = 0; cc < nCols; ++cc) {
                int e = colStart + cc;
                const ulonglong2* pe2 = (const ulonglong2*)(pes + e * 36);
                unsigned long long a01 = 0ull, a23 = 0ull;
#pragma unroll
                for (int j = 0; j < 8; ++j) {
                    ulonglong2 p2 = pe2[j];
                    FMA2(a01, p2.x, qp[j * 2], a01);
                    FMA2(a23, p2.y, qp[j * 2 + 1], a23);
                }
                float x0, x1, x2, x3;
                UNPACK2(x0, x1, a01);
                UNPACK2(x2, x3, a23);
                int v = e / 49, kl = e - v * 49;
                rcrow[v * 196 + kl] = (x0 + x1) + (x2 + x3);
            }
        }
    }
    __syncthreads();

    // =============== Phase 1d: softmax, 4 g-chains interleaved per v ========
    const float* rc_site = rc + site * 788;
    const float inv_sqn = 0.17677669529663687f;   // 1/sqrt(32)
#pragma unroll 1
    for (int v = 0; v < 4; ++v) {
        float s0[7], s1[7], s2[7], s3[7];
        float mx0 = -1e30f, mx1 = -1e30f, mx2 = -1e30f, mx3 = -1e30f;
        int vg0 = v * 4, vg1 = v * 4 + 1, vg2 = v * 4 + 2, vg3 = v * 4 + 3;
#pragma unroll
        for (int t = 0; t < 7; ++t) {
            if (valid[t]) {
                int kl = kl_t[t], m = m_t[t];
                s0[t] = (acc[0][t] + rc_site[vg0 * 49 + kl] + gs_s[vg0 * 4 + m]) * inv_sqn;
                s1[t] = (acc[1][t] + rc_site[vg1 * 49 + kl] + gs_s[vg1 * 4 + m]) * inv_sqn;
                s2[t] = (acc[2][t] + rc_site[vg2 * 49 + kl] + gs_s[vg2 * 4 + m]) * inv_sqn;
                s3[t] = (acc[3][t] + rc_site[vg3 * 49 + kl] + gs_s[vg3 * 4 + m]) * inv_sqn;
                mx0 = fmaxf(mx0, s0[t]); mx1 = fmaxf(mx1, s1[t]);
                mx2 = fmaxf(mx2, s2[t]); mx3 = fmaxf(mx3, s3[t]);
            } else { s0[t] = -1e30f; s1[t] = -1e30f; s2[t] = -1e30f; s3[t] = -1e30f; }
        }
#pragma unroll
        for (int o = 16; o; o >>= 1) {
            mx0 = fmaxf(mx0, __shfl_xor_sync(0xffffffffu, mx0, o));
            mx1 = fmaxf(mx1, __shfl_xor_sync(0xffffffffu, mx1, o));
            mx2 = fmaxf(mx2, __shfl_xor_sync(0xffffffffu, mx2, o));
            mx3 = fmaxf(mx3, __shfl_xor_sync(0xffffffffu, mx3, o));
        }
        float sum0 = 0.f, sum1 = 0.f, sum2 = 0.f, sum3 = 0.f;
#pragma unroll
        for (int t = 0; t < 7; ++t) {
            s0[t] = __expf(s0[t] - mx0); sum0 += s0[t];
            s1[t] = __expf(s1[t] - mx1); sum1 += s1[t];
            s2[t] = __expf(s2[t] - mx2); sum2 += s2[t];
            s3[t] = __expf(s3[t] - mx3); sum3 += s3[t];
        }
#pragma unroll
        for (int o = 16; o; o >>= 1) {
            sum0 += __shfl_xor_sync(0xffffffffu, sum0, o);
            sum1 += __shfl_xor_sync(0xffffffffu, sum1, o);
            sum2 += __shfl_xor_sync(0xffffffffu, sum2, o);
            sum3 += __shfl_xor_sync(0xffffffffu, sum3, o);
        }
        float inv0 = 1.f / sum0, inv1 = 1.f / sum1;
        float inv2 = 1.f / sum2, inv3 = 1.f / sum3;
#pragma unroll
        for (int t = 0; t < 7; ++t) {
            if (act[t]) {
                w_s[(lane + 32 * t) * 4 + v] =
                    s0[t] * inv0 + s1[t] * inv1 + s2[t] * inv2 + s3[t] * inv3;
            }
        }
    }

    // v-slab fully landed + all warps' w ready
    asm volatile("cp.async.wait_group 0;\n" ::: "memory");
    __syncthreads();

    // =============== Wout staging into rc area ==============================
    float* Wsm = rc;                 // [192 i][64 o]
    {
        int o = tid >> 3, i0 = tid & 7;
        const float* wsrc = Wout + o * 192;
#pragma unroll
        for (int k = 0; k < 24; ++k) {
            int i = i0 + k * 8;
            Wsm[i * 64 + o] = wsrc[i];
        }
    }

    // =============== Phase 2: combine via FFMA2 =============================
    float4* ovw = (float4*)(qs + site * 196);
    {
        // pass A: c = lane (0..31), full p range
        {
            int c = lane;
            unsigned long long a01 = 0ull, a23 = 0ull;
            for (int m = 0; m < 4; ++m) {
#pragma unroll
                for (int kk = 0; kk < 7; ++kk) {
                    const float* srow = slab + c * 401 + m * 100 + (ly + kk) * 10 + lx;
                    int p = m * 49 + kk * 7;
#pragma unroll
                    for (int ll = 0; ll < 7; ++ll) {
                        float sv = srow[ll];
                        unsigned long long svp;
                        PACK2(svp, sv, sv);
                        ulonglong2 wv = *(const ulonglong2*)(w_s + (p + ll) * 4);
                        FMA2(a01, wv.x, svp, a01);
                        FMA2(a23, wv.y, svp, a23);
                    }
                }
            }
            float a0, a1, a2, a3;
            UNPACK2(a0, a1, a01);
            UNPACK2(a2, a3, a23);
            ovw[c] = make_float4(a0, a1, a2, a3);
        }

        // pass B: c = 32 + (lane&15); half-warps split m-range, merge via shfl
        {
            int c = 32 + (lane & 15);
            int half = lane >> 4;
            unsigned long long a01 = 0ull, a23 = 0ull;
#pragma unroll
            for (int mm = 0; mm < 2; ++mm) {
                int m = half * 2 + mm;
#pragma unroll
                for (int kk = 0; kk < 7; ++kk) {
                    const float* srow = slab + c * 401 + m * 100 + (ly + kk) * 10 + lx;
                    int p = m * 49 + kk * 7;
#pragma unroll
                    for (int ll = 0; ll < 7; ++ll) {
                        float sv = srow[ll];
                        unsigned long long svp;
                        PACK2(svp, sv, sv);
                        ulonglong2 wv = *(const ulonglong2*)(w_s + (p + ll) * 4);
                        FMA2(a01, wv.x, svp, a01);
                        FMA2(a23, wv.y, svp, a23);
                    }
                }
            }
            float a0, a1, a2, a3;
            UNPACK2(a0, a1, a01);
            UNPACK2(a2, a3, a23);
            a0 += __shfl_xor_sync(0xffffffffu, a0, 16);
            a1 += __shfl_xor_sync(0xffffffffu, a1, 16);
            a2 += __shfl_xor_sync(0xffffffffu, a2, 16);
            a3 += __shfl_xor_sync(0xffffffffu, a3, 16);
            if (lane < 16) ovw[c] = make_float4(a0, a1, a2, a3);
        }
    }
    __syncthreads();   // Wsm staged by all warps; ov written

    // =============== Phase 3: per-h output GEMV -> g_part ===================
    {
        const float4* ov4 = (const float4*)(qs + site * 196);
        float av[4][2] = {};
#pragma unroll 4
        for (int c = 0; c < 48; ++c) {
            float4 o4 = ov4[c];
            const float* wr = Wsm + (c * 4 + h) * 64;
            float w0 = wr[lane], w1 = wr[lane + 32];
            av[0][0] += o4.x * w0; av[0][1] += o4.x * w1;
            av[1][0] += o4.y * w0; av[1][1] += o4.y * w1;
            av[2][0] += o4.z * w0; av[2][1] += o4.z * w1;
            av[3][0] += o4.w * w0; av[3][1] += o4.w * w1;
        }
        const int yx = (ty0 + ly) * 28 + tx0 + lx;
        int pbase = (h * 2 + b) * 3136 * 64;
#pragma unroll
        for (int v = 0; v < 4; ++v) {
            int addr = pbase + (v * 784 + yx) * 64;
            g_part[addr + lane]      = av[v][0];
            g_part[addr + lane + 32] = av[v][1];
        }
    }
}

// ---------------------------------------------------------------------------
// reduce: out[b][o][vyx] = bout[o] + sum_h g_part[h][b][vyx][o]
// 392 blocks x 256 threads.
// ---------------------------------------------------------------------------
__global__ void __launch_bounds__(256) reduce_kernel(
    const float* __restrict__ bout, float* __restrict__ out)
{
    __shared__ float Ts[64 * 17];
    int tid = threadIdx.x;
    int bb = blockIdx.x / 196;
    int vyx0 = (blockIdx.x % 196) * 16;

    int o = tid & 63;
    int i = tid >> 6;
    float bo = bout[o];
#pragma unroll
    for (int step = 0; step < 4; ++step) {
        int row = vyx0 + i + step * 4;
        float s = bo;
#pragma unroll
        for (int hh = 0; hh < 4; ++hh)
            s += g_part[((hh * 2 + bb) * 3136 + row) * 64 + o];
        Ts[o * 17 + i + step * 4] = s;
    }
    __syncthreads();

    float* obase = out + bb * 200704 + vyx0;
    for (int e = tid; e < 1024; e += 256) {
        int oo = e >> 4, ii = e & 15;
        obase[oo * 3136 + ii] = Ts[oo * 17 + ii];
    }
}

// ---------------------------------------------------------------------------
extern "C" void kernel_launch(void* const* d_in, const int* in_sizes, int n_in,
                              void* d_out, int out_size)
{
    const float* x    = (const float*)d_in[0];
    const float* Wq   = (const float*)d_in[1];  const float* bq = (const float*)d_in[2];
    const float* Wk   = (const float*)d_in[3];  const float* bk = (const float*)d_in[4];
    const float* Wv   = (const float*)d_in[5];  const float* bv = (const float*)d_in[6];
    const float* Wout = (const float*)d_in[7];  const float* bout = (const float*)d_in[8];
    const float* rw1  = (const float*)d_in[9];  const float* rb1 = (const float*)d_in[10];
    const float* rlg  = (const float*)d_in[11]; const float* rlb = (const float*)d_in[12];
    const float* rw2  = (const float*)d_in[13]; const float* rb2 = (const float*)d_in[14];
    const float* cw1  = (const float*)d_in[15]; const float* cb1 = (const float*)d_in[16];
    const float* clg  = (const float*)d_in[17]; const float* clb = (const float*)d_in[18];
    const float* cw2  = (const float*)d_in[19]; const float* cb2 = (const float*)d_in[20];
    const float* gemb = (const float*)d_in[21];
    const float* ridx = (const float*)d_in[22];
    const float* cidx = (const float*)d_in[23];
    const int*   gidx = (const int*)d_in[24];
    float* out = (float*)d_out;

    cudaFuncSetAttribute((const void*)attn_kernel,
                         cudaFuncAttributeMaxDynamicSharedMemorySize, ATTN_SMEM_BYTES);

    pe_kernel<<<1, 256>>>(rw1, rb1, rlg, rlb, rw2, rb2,
                          cw1, cb1, clg, clb, cw2, cb2,
                          ridx, cidx, gemb, gidx);
    proj_kernel<<<dim3(98, 9), 256>>>(x, Wq, bq, Wk, bk, Wv, bv);
    attn_kernel<<<392, 512, ATTN_SMEM_BYTES>>>(Wout);
    reduce_kernel<<<392, 256>>>(bout, out);
}

// round 17
// speedup vs baseline: 1.0824x; 1.0824x over previous
#include <cuda_runtime.h>
#include <math.h>

// Sizes: B=2, Cin=32, G=V=M=4, H=W=28, P=7, MID=48, HEADS=4, POS=16, Cout=64
// q/k/v layout: [(b*4+h)*4+g][yx][48c]
// g_pe: [v*49+kl][32c] (row 0..15, col 16..31)
// g_ge: [(v*4+g)*4+m][16c]
// g_part: [h][b][v*784+yx][64 o]  per-h partial output projection

__device__ float g_q[1204224];
__device__ float g_k[1204224];
__device__ float g_v[1204224];
__device__ float g_pe[6272];
__device__ float g_ge[1024];
__device__ float g_part[1605632];   // 4*2*3136*64

// ---------------------------------------------------------------------------
// PE MLP
// ---------------------------------------------------------------------------
__device__ __forceinline__ void pe_mlp(float tval,
    const float* __restrict__ w1, const float* __restrict__ b1,
    const float* __restrict__ lng, const float* __restrict__ lnb,
    const float* __restrict__ w2, const float* __restrict__ b2,
    float* outp)
{
    float hv[16];
    float mu = 0.f;
#pragma unroll
    for (int j = 0; j < 16; ++j) { hv[j] = tval * w1[j] + b1[j]; mu += hv[j]; }
    mu *= (1.f / 16.f);
    float var = 0.f;
#pragma unroll
    for (int j = 0; j < 16; ++j) { float d = hv[j] - mu; var += d * d; }
    var *= (1.f / 16.f);
    float rstd = rsqrtf(var + 1e-5f);
#pragma unroll
    for (int j = 0; j < 16; ++j) {
        float t = (hv[j] - mu) * rstd * lng[j] + lnb[j];
        hv[j] = t / (1.f + expf(-t));
    }
#pragma unroll
    for (int j = 0; j < 16; ++j) {
        float e = b2[j];
#pragma unroll
        for (int t = 0; t < 16; ++t) e += hv[t] * w2[j * 16 + t];
        outp[j] = e;
    }
}

__global__ void pe_kernel(
    const float* __restrict__ rw1, const float* __restrict__ rb1,
    const float* __restrict__ rlg, const float* __restrict__ rlb,
    const float* __restrict__ rw2, const float* __restrict__ rb2,
    const float* __restrict__ cw1, const float* __restrict__ cb1,
    const float* __restrict__ clg, const float* __restrict__ clb,
    const float* __restrict__ cw2, const float* __restrict__ cb2,
    const float* __restrict__ ridx, const float* __restrict__ cidx,
    const float* __restrict__ gemb, const int* __restrict__ gidx)
{
    int tid = threadIdx.x;
    if (tid < 196) {
        float er[16], ec[16];
        pe_mlp(ridx[tid], rw1, rb1, rlg, rlb, rw2, rb2, er);
        pe_mlp(cidx[tid], cw1, cb1, clg, clb, cw2, cb2, ec);
#pragma unroll
        for (int j = 0; j < 16; ++j) {
            g_pe[tid * 32 + j]      = er[j];
            g_pe[tid * 32 + 16 + j] = ec[j];
        }
    }
    for (int e = tid; e < 1024; e += blockDim.x) {
        int vgm = e >> 4, c = e & 15;
        g_ge[e] = gemb[gidx[vgm] * 16 + c];
    }
}

// ---------------------------------------------------------------------------
// proj: C[576 x 6272] = [Wq;Wk;Wv][576x32] * X[32x6272] -> g_q/k/v
// ---------------------------------------------------------------------------
__global__ void __launch_bounds__(256) proj_kernel(
    const float* __restrict__ x,
    const float* __restrict__ Wq, const float* __restrict__ bq,
    const float* __restrict__ Wk, const float* __restrict__ bk,
    const float* __restrict__ Wv, const float* __restrict__ bv)
{
    __shared__ float As[32 * 68];
    __shared__ float Bs[32 * 68];
    int tid = threadIdx.x;
    int n0 = blockIdx.x * 64;
    int r0 = blockIdx.y * 64;
    int which = r0 / 192;
    const float* Wm = (which == 0) ? Wq : (which == 1 ? Wk : Wv);
    const float* bias_p = (which == 0) ? bq : (which == 1 ? bk : bv);
    float* dst = (which == 0) ? g_q : (which == 1 ? g_k : g_v);
    int rbase = r0 - which * 192;
    int cbase = rbase >> 2;

#pragma unroll
    for (int k = 0; k < 8; ++k) {
        int i = tid + k * 256;
        int ci = i & 31, row = i >> 5;
        int r = rbase + row;
        int c_l = row >> 2, hh = row & 3;
        int s = (c_l >> 2) * 16 + hh * 4 + (c_l & 3);
        As[ci * 68 + s] = Wm[r * 32 + ci];
    }
#pragma unroll
    for (int k = 0; k < 8; ++k) {
        int i = tid + k * 256;
        int nl = i & 63, ci = i >> 6;
        int n = n0 + nl;
        int bb = n / 3136, rem = n - bb * 3136;
        Bs[ci * 68 + nl] = x[bb * 100352 + ci * 3136 + rem];
    }
    __syncthreads();

    int tx = tid & 15, ty = tid >> 4;
    float acc[4][4] = {};
#pragma unroll
    for (int ci = 0; ci < 32; ++ci) {
        float4 a4 = *(const float4*)&As[ci * 68 + ty * 4];
        float4 b4 = *(const float4*)&Bs[ci * 68 + tx * 4];
        float av[4] = { a4.x, a4.y, a4.z, a4.w };
        float bw[4] = { b4.x, b4.y, b4.z, b4.w };
#pragma unroll
        for (int u = 0; u < 4; ++u)
#pragma unroll
            for (int w = 0; w < 4; ++w) acc[u][w] += av[u] * bw[w];
    }

    int cq = ty >> 2, hh = ty & 3;
    int c0 = cbase + cq * 4;
    float b0 = bias_p[(c0 + 0) * 4 + hh];
    float b1 = bias_p[(c0 + 1) * 4 + hh];
    float b2 = bias_p[(c0 + 2) * 4 + hh];
    float b3 = bias_p[(c0 + 3) * 4 + hh];
#pragma unroll
    for (int w = 0; w < 4; ++w) {
        int n = n0 + tx * 4 + w;
        int bb = n / 3136, rem = n - bb * 3136;
        int gg = rem / 784, yx = rem - gg * 784;
        float4 val = make_float4(acc[0][w] + b0, acc[1][w] + b1,
                                 acc[2][w] + b2, acc[3][w] + b3);
        *(float4*)&dst[(((bb * 4 + hh) * 4 + gg) * 784 + yx) * 48 + c0] = val;
    }
}

// ---------------------------------------------------------------------------
// attn: one block per (b,h, 4x4 pixel tile). 512 threads = 16 warps = 1 site/warp.
// ges padded to stride 17 (kills 32-way bank conflict in gs loop).
// ---------------------------------------------------------------------------
#define SM_PE    0        // [196][36]
#define SM_GE    7056     // [64][17] padded
#define SM_QS    8144     // [16 sites][196] (reused as ov[c][4v] in combine)
#define SM_SLAB  11280    // [48 c][401]  pos = m*100 + sy*10 + sx
#define SM_RC    30528    // [16 sites][788]; reused as Wout staging after softmax
#define SM_SCR   43136    // per-warp: w 784 | gs 64 = 848
#define SCR_WARP 848
#define ATTN_SMEM_FLOATS (SM_SCR + 16 * SCR_WARP)  // 56704
#define ATTN_SMEM_BYTES  (ATTN_SMEM_FLOATS * 4)    // 226816

// synchronous slab loader (k)
__device__ __forceinline__ void load_slab(float* slab, const float* __restrict__ src,
                                          int bh, int ty0, int tx0, int tid)
{
    if (tid < 480) {
        int c  = tid % 48;
        int sx = tid / 48;                       // 0..9
        int xx = tx0 - 3 + sx;
        bool xok = (unsigned)xx < 28u;
        float* sdst = slab + c * 401 + sx;
        const float* gbase = src + (bh * 4) * 37632 + xx * 48 + c;
#pragma unroll
        for (int m = 0; m < 4; ++m) {
#pragma unroll
            for (int sy = 0; sy < 10; ++sy) {
                int y = ty0 - 3 + sy;
                float val = 0.f;
                if (xok && (unsigned)y < 28u)
                    val = gbase[m * 37632 + y * 1344];
                sdst[m * 100 + sy * 10] = val;
            }
        }
    }
}

// async slab loader (v)
__device__ __forceinline__ void load_slab_async(float* slab, const float* __restrict__ src,
                                                int bh, int ty0, int tx0, int tid)
{
    if (tid < 480) {
        int c  = tid % 48;
        int sx = tid / 48;
        int xx = tx0 - 3 + sx;
        bool xok = (unsigned)xx < 28u;
        int xc = xok ? xx : 0;
        unsigned int sdst = (unsigned int)__cvta_generic_to_shared(slab + c * 401 + sx);
        const float* gbase = src + (bh * 4) * 37632 + xc * 48 + c;
#pragma unroll
        for (int m = 0; m < 4; ++m) {
#pragma unroll
            for (int sy = 0; sy < 10; ++sy) {
                int y = ty0 - 3 + sy;
                bool ok = xok && ((unsigned)y < 28u);
                int yc = ok ? y : 0;
                const float* gp = gbase + m * 37632 + yc * 1344;
                unsigned int sa = sdst + (unsigned int)((m * 100 + sy * 10) * 4);
                int sz = ok ? 4 : 0;
                asm volatile("cp.async.ca.shared.global [%0], [%1], 4, %2;\n"
                             :: "r"(sa), "l"(gp), "r"(sz));
            }
        }
    }
    asm volatile("cp.async.commit_group;\n" ::: "memory");
}

__global__ void __launch_bounds__(512, 1) attn_kernel(const float* __restrict__ Wout)
{
    extern __shared__ float sm[];
    float* pes  = sm + SM_PE;
    float* ges  = sm + SM_GE;
    float* qs   = sm + SM_QS;
    float* slab = sm + SM_SLAB;
    float* rc   = sm + SM_RC;

    const int tid  = threadIdx.x, lane = tid & 31, warp = tid >> 5;
    const int tile = blockIdx.x % 49;
    const int bh   = blockIdx.x / 49;
    const int b    = bh >> 2, h = bh & 3;
    const int ty0  = (tile / 7) * 4, tx0 = (tile % 7) * 4;

    for (int i = tid; i < 6272; i += 512) pes[(i >> 5) * 36 + (i & 31)] = g_pe[i];
    for (int i = tid; i < 1024; i += 512) ges[(i >> 4) * 17 + (i & 15)] = g_ge[i];
    for (int i = tid; i < 3072; i += 512) {
        int site = i / 192, r = i - site * 192, gg = r / 48, c = r - gg * 48;
        int yx = (ty0 + (site >> 2)) * 28 + tx0 + (site & 3);
        qs[site * 196 + r] = g_q[((bh * 4 + gg) * 784 + yx) * 48 + c];
    }
    load_slab(slab, g_k, bh, ty0, tx0, tid);
    __syncthreads();

    float* scr  = sm + SM_SCR + warp * SCR_WARP;
    float* w_s  = scr;            // 784: [196 p][4 v]
    float* gs_s = scr + 784;      // 64 : [v][g][4 m]

    const int site = warp;
    const int ly = site >> 2, lx = site & 3;
    const float* qsi = qs + site * 196;

    // =============== Phase 1a: group scores gs[v][g][m] (per-warp) =========
#pragma unroll
    for (int u = 0; u < 2; ++u) {
        int e = lane * 2 + u;
        int gg = (e >> 2) & 3;
        float a = 0.f;
#pragma unroll
        for (int c = 0; c < 16; ++c)
            a += qsi[gg * 48 + 32 + c] * ges[e * 17 + c];
        gs_s[e] = a;
    }

    // per-lane entry mapping: p = lane + 32*t over 196 = 4m x 49kl
    int kl_t[7], m_t[7], pos_t[7];
    bool valid[7], act[7];
#pragma unroll
    for (int t = 0; t < 7; ++t) {
        int p = lane + 32 * t;
        act[t] = (p < 196);
        int pc = act[t] ? p : 0;
        int m = pc / 49, kl = pc - m * 49, kk = kl / 7, ll = kl - kk * 7;
        kl_t[t] = kl; m_t[t] = m;
        pos_t[t] = m * 100 + (ly + kk) * 10 + (lx + ll);
        int y = ty0 + ly + kk - 3, xx = tx0 + lx + ll - 3;
        valid[t] = act[t] && ((unsigned)y < 28u) && ((unsigned)xx < 28u);
    }

    // =============== Phase 1b: content[g][t] = sum_c q[g][c]*k[c][pos_t] ===
    float acc[4][7];
#pragma unroll
    for (int gg = 0; gg < 4; ++gg)
#pragma unroll
        for (int t = 0; t < 7; ++t) acc[gg][t] = 0.f;
    {
        const float4* q4p = (const float4*)qsi;
        for (int c4 = 0; c4 < 12; ++c4) {
            float4 qa = q4p[c4], qb = q4p[12 + c4], qc = q4p[24 + c4], qd = q4p[36 + c4];
            float qr[4][4] = { { qa.x, qa.y, qa.z, qa.w },
                               { qb.x, qb.y, qb.z, qb.w },
                               { qc.x, qc.y, qc.z, qc.w },
                               { qd.x, qd.y, qd.z, qd.w } };
#pragma unroll
            for (int u = 0; u < 4; ++u) {
                const float* sr = slab + (c4 * 4 + u) * 401;
#pragma unroll
                for (int t = 0; t < 7; ++t) {
                    float sv = sr[pos_t[t]];
                    acc[0][t] += qr[0][u] * sv; acc[1][t] += qr[1][u] * sv;
                    acc[2][t] += qr[2][u] * sv; acc[3][t] += qr[3][u] * sv;
                }
            }
        }
    }

    // k-slab reads complete; start async v-slab refill (overlaps rc + softmax)
    __syncthreads();
    load_slab_async(slab, g_v, bh, ty0, tx0, tid);

    // =============== Phase 1c: cooperative rc ===============================
    {
        int colStart = warp * 12 + (warp < 4 ? warp : 4);
        int nCols = (warp < 4) ? 13 : 12;
#pragma unroll 1
        for (int pass = 0; pass < 2; ++pass) {
            int row = pass * 32 + lane;          // (site,g)
            int rsite = row >> 2, rg = row & 3;
            float qreg[32];
            const float4* q4 = (const float4*)(qs + rsite * 196 + rg * 48);
#pragma unroll
            for (int j = 0; j < 8; ++j) {
                float4 t4 = q4[j];
                qreg[j * 4 + 0] = t4.x; qreg[j * 4 + 1] = t4.y;
                qreg[j * 4 + 2] = t4.z; qreg[j * 4 + 3] = t4.w;
            }
            float* rcrow = rc + rsite * 788 + rg * 49;
            for (int cc = 0; cc < nCols; ++cc) {
                int e = colStart + cc;
                const float4* pe4 = (const float4*)(pes + e * 36);
                float a = 0.f;
#pragma unroll
                for (int j = 0; j < 8; ++j) {
                    float4 p4 = pe4[j];
                    a += p4.x * qreg[j * 4 + 0] + p4.y * qreg[j * 4 + 1]
                       + p4.z * qreg[j * 4 + 2] + p4.w * qreg[j * 4 + 3];
                }
                int v = e / 49, kl = e - v * 49;
                rcrow[v * 196 + kl] = a;
            }
        }
    }
    __syncthreads();

    // =============== Phase 1d: softmax, 4 g-chains interleaved per v ========
    const float* rc_site = rc + site * 788;
    const float inv_sqn = 0.17677669529663687f;   // 1/sqrt(32)
#pragma unroll 1
    for (int v = 0; v < 4; ++v) {
        float s0[7], s1[7], s2[7], s3[7];
        float mx0 = -1e30f, mx1 = -1e30f, mx2 = -1e30f, mx3 = -1e30f;
        int vg0 = v * 4, vg1 = v * 4 + 1, vg2 = v * 4 + 2, vg3 = v * 4 + 3;
#pragma unroll
        for (int t = 0; t < 7; ++t) {
            if (valid[t]) {
                int kl = kl_t[t], m = m_t[t];
                s0[t] = (acc[0][t] + rc_site[vg0 * 49 + kl] + gs_s[vg0 * 4 + m]) * inv_sqn;
                s1[t] = (acc[1][t] + rc_site[vg1 * 49 + kl] + gs_s[vg1 * 4 + m]) * inv_sqn;
                s2[t] = (acc[2][t] + rc_site[vg2 * 49 + kl] + gs_s[vg2 * 4 + m]) * inv_sqn;
                s3[t] = (acc[3][t] + rc_site[vg3 * 49 + kl] + gs_s[vg3 * 4 + m]) * inv_sqn;
                mx0 = fmaxf(mx0, s0[t]); mx1 = fmaxf(mx1, s1[t]);
                mx2 = fmaxf(mx2, s2[t]); mx3 = fmaxf(mx3, s3[t]);
            } else { s0[t] = -1e30f; s1[t] = -1e30f; s2[t] = -1e30f; s3[t] = -1e30f; }
        }
#pragma unroll
        for (int o = 16; o; o >>= 1) {
            mx0 = fmaxf(mx0, __shfl_xor_sync(0xffffffffu, mx0, o));
            mx1 = fmaxf(mx1, __shfl_xor_sync(0xffffffffu, mx1, o));
            mx2 = fmaxf(mx2, __shfl_xor_sync(0xffffffffu, mx2, o));
            mx3 = fmaxf(mx3, __shfl_xor_sync(0xffffffffu, mx3, o));
        }
        float sum0 = 0.f, sum1 = 0.f, sum2 = 0.f, sum3 = 0.f;
#pragma unroll
        for (int t = 0; t < 7; ++t) {
            s0[t] = __expf(s0[t] - mx0); sum0 += s0[t];
            s1[t] = __expf(s1[t] - mx1); sum1 += s1[t];
            s2[t] = __expf(s2[t] - mx2); sum2 += s2[t];
            s3[t] = __expf(s3[t] - mx3); sum3 += s3[t];
        }
#pragma unroll
        for (int o = 16; o; o >>= 1) {
            sum0 += __shfl_xor_sync(0xffffffffu, sum0, o);
            sum1 += __shfl_xor_sync(0xffffffffu, sum1, o);
            sum2 += __shfl_xor_sync(0xffffffffu, sum2, o);
            sum3 += __shfl_xor_sync(0xffffffffu, sum3, o);
        }
        float inv0 = 1.f / sum0, inv1 = 1.f / sum1;
        float inv2 = 1.f / sum2, inv3 = 1.f / sum3;
#pragma unroll
        for (int t = 0; t < 7; ++t) {
            if (act[t]) {
                w_s[(lane + 32 * t) * 4 + v] =
                    s0[t] * inv0 + s1[t] * inv1 + s2[t] * inv2 + s3[t] * inv3;
            }
        }
    }

    // v-slab fully landed + all warps' w ready
    asm volatile("cp.async.wait_group 0;\n" ::: "memory");
    __syncthreads();

    // =============== Wout staging into rc area ==============================
    float* Wsm = rc;                 // [192 i][64 o]
    {
        int o = tid >> 3, i0 = tid & 7;
        const float* wsrc = Wout + o * 192;
#pragma unroll
        for (int k = 0; k < 24; ++k) {
            int i = i0 + k * 8;
            Wsm[i * 64 + o] = wsrc[i];
        }
    }

    // =============== Phase 2: combine o[c][v] = sum_p w[p][v]*vslab[c][pos] =
    float4* ovw = (float4*)(qs + site * 196);
    {
        const float4* w4 = (const float4*)w_s;

        // pass A: c = lane (0..31), full p range
        {
            int c = lane;
            float a0 = 0.f, a1 = 0.f, a2 = 0.f, a3 = 0.f;
            for (int m = 0; m < 4; ++m) {
#pragma unroll
                for (int kk = 0; kk < 7; ++kk) {
                    const float* srow = slab + c * 401 + m * 100 + (ly + kk) * 10 + lx;
                    int p = m * 49 + kk * 7;
#pragma unroll
                    for (int ll = 0; ll < 7; ++ll) {
                        float sv = srow[ll];
                        float4 wv = w4[p + ll];
                        a0 += wv.x * sv; a1 += wv.y * sv;
                        a2 += wv.z * sv; a3 += wv.w * sv;
                    }
                }
            }
            ovw[c] = make_float4(a0, a1, a2, a3);
        }

        // pass B: c = 32 + (lane&15); half-warps split m-range, merge via shfl
        {
            int c = 32 + (lane & 15);
            int half = lane >> 4;
            float a0 = 0.f, a1 = 0.f, a2 = 0.f, a3 = 0.f;
#pragma unroll
            for (int mm = 0; mm < 2; ++mm) {
                int m = half * 2 + mm;
#pragma unroll
                for (int kk = 0; kk < 7; ++kk) {
                    const float* srow = slab + c * 401 + m * 100 + (ly + kk) * 10 + lx;
                    int p = m * 49 + kk * 7;
#pragma unroll
                    for (int ll = 0; ll < 7; ++ll) {
                        float sv = srow[ll];
                        float4 wv = w4[p + ll];
                        a0 += wv.x * sv; a1 += wv.y * sv;
                        a2 += wv.z * sv; a3 += wv.w * sv;
                    }
                }
            }
            a0 += __shfl_xor_sync(0xffffffffu, a0, 16);
            a1 += __shfl_xor_sync(0xffffffffu, a1, 16);
            a2 += __shfl_xor_sync(0xffffffffu, a2, 16);
            a3 += __shfl_xor_sync(0xffffffffu, a3, 16);
            if (lane < 16) ovw[c] = make_float4(a0, a1, a2, a3);
        }
    }
    __syncthreads();   // Wsm staged by all warps; ov written

    // =============== Phase 3: per-h output GEMV -> g_part ===================
    {
        const float4* ov4 = (const float4*)(qs + site * 196);
        float av[4][2] = {};
#pragma unroll 4
        for (int c = 0; c < 48; ++c) {
            float4 o4 = ov4[c];
            const float* wr = Wsm + (c * 4 + h) * 64;
            float w0 = wr[lane], w1 = wr[lane + 32];
            av[0][0] += o4.x * w0; av[0][1] += o4.x * w1;
            av[1][0] += o4.y * w0; av[1][1] += o4.y * w1;
            av[2][0] += o4.z * w0; av[2][1] += o4.z * w1;
            av[3][0] += o4.w * w0; av[3][1] += o4.w * w1;
        }
        const int yx = (ty0 + ly) * 28 + tx0 + lx;
        int pbase = (h * 2 + b) * 3136 * 64;
#pragma unroll
        for (int v = 0; v < 4; ++v) {
            int addr = pbase + (v * 784 + yx) * 64;
            g_part[addr + lane]      = av[v][0];
            g_part[addr + lane + 32] = av[v][1];
        }
    }
}

// ---------------------------------------------------------------------------
// reduce: out[b][o][vyx] = bout[o] + sum_h g_part[h][b][vyx][o]
// 392 blocks x 256 threads.
// ---------------------------------------------------------------------------
__global__ void __launch_bounds__(256) reduce_kernel(
    const float* __restrict__ bout, float* __restrict__ out)
{
    __shared__ float Ts[64 * 17];
    int tid = threadIdx.x;
    int bb = blockIdx.x / 196;
    int vyx0 = (blockIdx.x % 196) * 16;

    int o = tid & 63;
    int i = tid >> 6;
    float bo = bout[o];
#pragma unroll
    for (int step = 0; step < 4; ++step) {
        int row = vyx0 + i + step * 4;
        float s = bo;
#pragma unroll
        for (int hh = 0; hh < 4; ++hh)
            s += g_part[((hh * 2 + bb) * 3136 + row) * 64 + o];
        Ts[o * 17 + i + step * 4] = s;
    }
    __syncthreads();

    float* obase = out + bb * 200704 + vyx0;
    for (int e = tid; e < 1024; e += 256) {
        int oo = e >> 4, ii = e & 15;
        obase[oo * 3136 + ii] = Ts[oo * 17 + ii];
    }
}

// ---------------------------------------------------------------------------
extern "C" void kernel_launch(void* const* d_in, const int* in_sizes, int n_in,
                              void* d_out, int out_size)
{
    const float* x    = (const float*)d_in[0];
    const float* Wq   = (const float*)d_in[1];  const float* bq = (const float*)d_in[2];
    const float* Wk   = (const float*)d_in[3];  const float* bk = (const float*)d_in[4];
    const float* Wv   = (const float*)d_in[5];  const float* bv = (const float*)d_in[6];
    const float* Wout = (const float*)d_in[7];  const float* bout = (const float*)d_in[8];
    const float* rw1  = (const float*)d_in[9];  const float* rb1 = (const float*)d_in[10];
    const float* rlg  = (const float*)d_in[11]; const float* rlb = (const float*)d_in[12];
    const float* rw2  = (const float*)d_in[13]; const float* rb2 = (const float*)d_in[14];
    const float* cw1  = (const float*)d_in[15]; const float* cb1 = (const float*)d_in[16];
    const float* clg  = (const float*)d_in[17]; const float* clb = (const float*)d_in[18];
    const float* cw2  = (const float*)d_in[19]; const float* cb2 = (const float*)d_in[20];
    const float* gemb = (const float*)d_in[21];
    const float* ridx = (const float*)d_in[22];
    const float* cidx = (const float*)d_in[23];
    const int*   gidx = (const int*)d_in[24];
    float* out = (float*)d_out;

    cudaFuncSetAttribute((const void*)attn_kernel,
                         cudaFuncAttributeMaxDynamicSharedMemorySize, ATTN_SMEM_BYTES);

    pe_kernel<<<1, 256>>>(rw1, rb1, rlg, rlb, rw2, rb2,
                          cw1, cb1, clg, clb, cw2, cb2,
                          ridx, cidx, gemb, gidx);
    proj_kernel<<<dim3(98, 9), 256>>>(x, Wq, bq, Wk, bk, Wv, bv);
    attn_kernel<<<392, 512, ATTN_SMEM_BYTES>>>(Wout);
    reduce_kernel<<<392, 256>>>(bout, out);
}